// round 6
// baseline (speedup 1.0000x reference)
#include <cuda_runtime.h>
#include <cuda_bf16.h>
#include <cstdint>

#define NN      10000
#define EE      30000
#define FEDGE   8
#define EMB     64
#define HID     16
#define NG      64
#define NCOL    1088   // 1024 P | 64 Q
#define QOFF    1024

// ---------------- scratch (device globals) --------------------------------
__device__ __align__(128) float g_h0[EE * HID];
__device__ __align__(128) float g_h1[EE * HID];
__device__ __align__(128) float g_PQ[(size_t)NN * NCOL];
__device__ __align__(128) float g_agg0[NN * EMB];
__device__ __align__(128) float g_agg1[NN * EMB];
__device__ __align__(128) float g_agg2[NN * EMB];
__device__ __align__(128) float g_xr0[NN * EMB];
__device__ __align__(128) float g_xr1[NN * EMB];
__device__ __align__(128) float g_xr2[NN * EMB];
// pre-converted bf16 hi/lo B matrices, [tile][o][i] layout
__device__ __align__(128) ushort g_W0h[18 * 64 * 32], g_W0l[18 * 64 * 32]; // conv0 P,Q + root0(tile 17)
__device__ __align__(128) ushort g_W1h[17 * 64 * 64], g_W1l[17 * 64 * 64]; // convs 1&2 P,Q (shared)
__device__ __align__(128) ushort g_R1h[64 * 64], g_R1l[64 * 64];
__device__ __align__(128) ushort g_R2h[64 * 64], g_R2l[64 * 64];
__device__ __align__(128) float g_pool[NG * EMB];
__device__ unsigned g_cnt = 0;

// ---------------- helpers --------------------------------------------------
__device__ __forceinline__ uint32_t smem_u32(const void* p) {
    uint32_t a;
    asm("{ .reg .u64 t; cvta.to.shared.u64 t, %1; cvt.u32.u64 %0, t; }" : "=r"(a) : "l"(p));
    return a;
}
__device__ __forceinline__ void ldmx4(uint32_t* r, uint32_t addr) {
    asm volatile("ldmatrix.sync.aligned.m8n8.x4.shared.b16 {%0,%1,%2,%3}, [%4];"
        : "=r"(r[0]), "=r"(r[1]), "=r"(r[2]), "=r"(r[3]) : "r"(addr));
}
__device__ __forceinline__ void mma_bf16(float* d, const uint32_t* a,
                                         uint32_t b0, uint32_t b1) {
    asm volatile("mma.sync.aligned.m16n8k16.row.col.f32.bf16.bf16.f32 "
        "{%0,%1,%2,%3}, {%4,%5,%6,%7}, {%8,%9}, {%0,%1,%2,%3};"
        : "+f"(d[0]), "+f"(d[1]), "+f"(d[2]), "+f"(d[3])
        : "r"(a[0]), "r"(a[1]), "r"(a[2]), "r"(a[3]), "r"(b0), "r"(b1));
}
__device__ __forceinline__ void split_pack(float fx, float fy,
                                           uint32_t& hi, uint32_t& lo) {
    __nv_bfloat16 hx = __float2bfloat16(fx), hy = __float2bfloat16(fy);
    hi = ((uint32_t)__bfloat16_as_ushort(hy) << 16) | __bfloat16_as_ushort(hx);
    __nv_bfloat16 lx = __float2bfloat16(fx - __bfloat162float(hx));
    __nv_bfloat16 ly = __float2bfloat16(fy - __bfloat162float(hy));
    lo = ((uint32_t)__bfloat16_as_ushort(ly) << 16) | __bfloat16_as_ushort(lx);
}
__device__ __forceinline__ void split_us(float v, ushort& hi, ushort& lo) {
    __nv_bfloat16 h = __float2bfloat16(v);
    hi = __bfloat16_as_ushort(h);
    lo = __bfloat16_as_ushort(__float2bfloat16(v - __bfloat162float(h)));
}

// ---------------- prep: transpose + bf16-split B, edge MLP hiddens ---------
// blocks 0..17 : conv0 tiles (0..16 = P,Q ; 17 = root0), D=32
// blocks 18..34: conv1 P,Q tiles, D=64
// block  35    : root1      36: root2
// blocks 37.. : edge MLP hiddens
#define TR_BLOCKS 37
#define EH_BLOCKS ((EE + 255) / 256)

__global__ __launch_bounds__(256) void prep_kernel(
    const float* __restrict__ ea,
    const float* __restrict__ nn0_w1, const float* __restrict__ nn0_b1,
    const float* __restrict__ nn0_w2, const float* __restrict__ nn0_b2,
    const float* __restrict__ nn1_w1, const float* __restrict__ nn1_b1,
    const float* __restrict__ nn1_w2, const float* __restrict__ nn1_b2,
    const float* __restrict__ root0, const float* __restrict__ root1,
    const float* __restrict__ root2)
{
    int tid = threadIdx.x;
    int b = blockIdx.x;

    if (b < TR_BLOCKS) {
        __shared__ float ts[64 * 65];
        const float* src;
        ushort *dsth, *dstl;
        int D;
        if (b < 17) {
            D = 32; src = (b < 16) ? nn0_w2 + b * 2048 : nn0_b2;
            dsth = g_W0h + b * 2048; dstl = g_W0l + b * 2048;
        } else if (b == 17) {
            D = 32; src = root0;
            dsth = g_W0h + 17 * 2048; dstl = g_W0l + 17 * 2048;
        } else if (b < 35) {
            int bb = b - 18; D = 64;
            src = (bb < 16) ? nn1_w2 + bb * 4096 : nn1_b2;
            dsth = g_W1h + bb * 4096; dstl = g_W1l + bb * 4096;
        } else if (b == 35) { D = 64; src = root1; dsth = g_R1h; dstl = g_R1l; }
        else               { D = 64; src = root2; dsth = g_R2h; dstl = g_R2l; }

        for (int idx = tid; idx < 64 * D; idx += 256) {
            int o = idx & 63, i = idx >> 6;
            ts[o * 65 + i] = src[i * 64 + o];     // coalesced over o
        }
        __syncthreads();
        for (int idx = tid; idx < 64 * D; idx += 256) {
            int i = idx & (D - 1), o = idx / D;
            ushort hi, lo;
            split_us(ts[o * 65 + i], hi, lo);
            dsth[idx] = hi;
            dstl[idx] = lo;
        }
        return;
    }

    __shared__ float sw0[FEDGE * HID], sw1[FEDGE * HID];
    __shared__ float sb0[HID], sb1[HID];
    if (tid < FEDGE * HID) { sw0[tid] = nn0_w1[tid]; sw1[tid] = nn1_w1[tid]; }
    if (tid < HID)         { sb0[tid] = nn0_b1[tid]; sb1[tid] = nn1_b1[tid]; }
    __syncthreads();

    int e = (b - TR_BLOCKS) * 256 + tid;
    if (e >= EE) return;
    const float4* p = reinterpret_cast<const float4*>(ea + (size_t)e * FEDGE);
    float4 v0 = p[0], v1 = p[1];
    float a[8] = {v0.x, v0.y, v0.z, v0.w, v1.x, v1.y, v1.z, v1.w};
#pragma unroll
    for (int h = 0; h < HID; h++) {
        float s0 = sb0[h], s1 = sb1[h];
#pragma unroll
        for (int j = 0; j < FEDGE; j++) {
            s0 += a[j] * sw0[j * HID + h];
            s1 += a[j] * sw1[j * HID + h];
        }
        g_h0[e * HID + h] = fmaxf(s0, 0.f);
        g_h1[e * HID + h] = fmaxf(s1, 0.f);
    }
}

// ---------------- fused HMMA GEMM (ks-outer, 2 resident B tiles) ----------
// [x | relu(agg+xr+bias)] (128 rows) @ WT^T, 2 column tiles/block.
// Tiles 0..16 -> g_PQ, tile 17 -> g_xr (root product). Zeroes next agg.
template <int D, int MODE>
__global__ __launch_bounds__(256, 2) void gemm_fused_kernel(
    const float* __restrict__ xin, const float* __restrict__ biasin)
{
    const int SD = D + 8;
    const int CPT = D / 8;
    extern __shared__ ushort smu[];
    ushort* Ah = smu;                   // 128*SD
    ushort* Al = Ah + 128 * SD;
    ushort* Bh = Al + 128 * SD;         // 2 tiles x 64*SD
    ushort* Bl = Bh + 2 * 64 * SD;
    __shared__ float sbias[64];

    const float* __restrict__ aggin = (MODE == 1) ? g_agg0 : g_agg1;
    const float* __restrict__ xrin  = (MODE == 1) ? g_xr0  : g_xr1;
    float* __restrict__ aggz  = (MODE == 0) ? g_agg0 : (MODE == 1 ? g_agg1 : g_agg2);
    float* __restrict__ xrout = (MODE == 0) ? g_xr0  : (MODE == 1 ? g_xr1  : g_xr2);
    const ushort* __restrict__ WTh = (MODE == 0) ? g_W0h : g_W1h;
    const ushort* __restrict__ WTl = (MODE == 0) ? g_W0l : g_W1l;
    const ushort* __restrict__ RTh = (MODE == 0) ? (g_W0h + 17 * 2048)
                                                 : (MODE == 1 ? g_R1h : g_R2h);
    const ushort* __restrict__ RTl = (MODE == 0) ? (g_W0l + 17 * 2048)
                                                 : (MODE == 1 ? g_R1l : g_R2l);

    int tid = threadIdx.x, wid = tid >> 5, l = tid & 31;
    int wm = wid & 3, wn = wid >> 2;
    int m0 = blockIdx.y * 128;
    int t0 = blockIdx.x * 2;

    // zero next agg buffer
    {
        int nthr = gridDim.x * gridDim.y * 256;
        for (int i = (blockIdx.y * gridDim.x + blockIdx.x) * 256 + tid;
             i < NN * EMB; i += nthr)
            aggz[i] = 0.f;
    }
    if (MODE && tid < 64) sbias[tid] = biasin[tid];

    // ---- stage B: both tiles, plain uint4 copies of pre-split bf16 ----
#pragma unroll
    for (int ti = 0; ti < 2; ti++) {
        int ct = t0 + ti;
        const ushort* bh = (ct == 17) ? RTh : WTh + (size_t)ct * 64 * D;
        const ushort* bl = (ct == 17) ? RTl : WTl + (size_t)ct * 64 * D;
        for (int idx = tid; idx < 64 * D / 8; idx += 256) {
            int r = idx / CPT, cb8 = idx % CPT;
            uint4 vh = *reinterpret_cast<const uint4*>(bh + r * D + cb8 * 8);
            uint4 vl = *reinterpret_cast<const uint4*>(bl + r * D + cb8 * 8);
            *reinterpret_cast<uint4*>(Bh + ti * 64 * SD + r * SD + cb8 * 8) = vh;
            *reinterpret_cast<uint4*>(Bl + ti * 64 * SD + r * SD + cb8 * 8) = vl;
        }
    }
    if (MODE) __syncthreads();   // sbias visible (B copies need no order yet)

    // ---- stage A once (full D), fp32 -> bf16 hi/lo ----
    for (int idx = tid; idx < 128 * CPT; idx += 256) {
        int r = idx / CPT, cb = (idx % CPT) * 8;
        int n = m0 + r;
        bool v = (n < NN);
        float vals[8];
        if (MODE == 0) {
            float4 a0 = make_float4(0.f, 0.f, 0.f, 0.f), a1 = a0;
            if (v) {
                a0 = *reinterpret_cast<const float4*>(xin + (size_t)n * D + cb);
                a1 = *reinterpret_cast<const float4*>(xin + (size_t)n * D + cb + 4);
            }
            vals[0]=a0.x; vals[1]=a0.y; vals[2]=a0.z; vals[3]=a0.w;
            vals[4]=a1.x; vals[5]=a1.y; vals[6]=a1.z; vals[7]=a1.w;
        } else {
            float4 g0 = make_float4(0.f,0.f,0.f,0.f), g1 = g0, r0 = g0, r1 = g0;
            if (v) {
                g0 = *reinterpret_cast<const float4*>(aggin + (size_t)n * EMB + cb);
                g1 = *reinterpret_cast<const float4*>(aggin + (size_t)n * EMB + cb + 4);
                r0 = *reinterpret_cast<const float4*>(xrin + (size_t)n * EMB + cb);
                r1 = *reinterpret_cast<const float4*>(xrin + (size_t)n * EMB + cb + 4);
            }
            vals[0] = fmaxf(g0.x + r0.x + sbias[cb+0], 0.f);
            vals[1] = fmaxf(g0.y + r0.y + sbias[cb+1], 0.f);
            vals[2] = fmaxf(g0.z + r0.z + sbias[cb+2], 0.f);
            vals[3] = fmaxf(g0.w + r0.w + sbias[cb+3], 0.f);
            vals[4] = fmaxf(g1.x + r1.x + sbias[cb+4], 0.f);
            vals[5] = fmaxf(g1.y + r1.y + sbias[cb+5], 0.f);
            vals[6] = fmaxf(g1.z + r1.z + sbias[cb+6], 0.f);
            vals[7] = fmaxf(g1.w + r1.w + sbias[cb+7], 0.f);
        }
        uint32_t* ah32 = reinterpret_cast<uint32_t*>(Ah);
        uint32_t* al32 = reinterpret_cast<uint32_t*>(Al);
        int base = (r * SD + cb) >> 1;
#pragma unroll
        for (int j = 0; j < 4; j++) {
            uint32_t hi, lo;
            split_pack(vals[2*j], vals[2*j+1], hi, lo);
            ah32[base + j] = hi;
            al32[base + j] = lo;
        }
    }
    __syncthreads();

    uint32_t aAh = smem_u32(Ah), aAl = smem_u32(Al);
    uint32_t aBh = smem_u32(Bh), aBl = smem_u32(Bl);

    float acc[2][2][4][4];
#pragma unroll
    for (int ti = 0; ti < 2; ti++)
#pragma unroll
        for (int mi = 0; mi < 2; mi++)
#pragma unroll
            for (int nf = 0; nf < 4; nf++)
#pragma unroll
                for (int q = 0; q < 4; q++) acc[ti][mi][nf][q] = 0.f;

#pragma unroll
    for (int ks = 0; ks < D; ks += 16) {
        uint32_t ahf[2][4], alf[2][4];
#pragma unroll
        for (int mi = 0; mi < 2; mi++) {
            uint32_t off = ((uint32_t)(wm * 32 + mi * 16 + (l & 15)) * SD
                            + ks + (l >> 4) * 8) * 2;
            ldmx4(ahf[mi], aAh + off);
            ldmx4(alf[mi], aAl + off);
        }
#pragma unroll
        for (int ti = 0; ti < 2; ti++) {
            uint32_t bhf[8], blf[8];
#pragma unroll
            for (int g = 0; g < 2; g++) {
                uint32_t off = (uint32_t)(ti * 64 * SD) * 2
                    + ((uint32_t)(wn * 32 + g * 16 + (l & 7) + ((l >> 4) & 1) * 8) * SD
                       + ks + ((l >> 3) & 1) * 8) * 2;
                ldmx4(bhf + g * 4, aBh + off);
                ldmx4(blf + g * 4, aBl + off);
            }
#pragma unroll
            for (int mi = 0; mi < 2; mi++)
#pragma unroll
                for (int nf = 0; nf < 4; nf++) {
                    mma_bf16(acc[ti][mi][nf], ahf[mi], bhf[nf*2], bhf[nf*2+1]);
                    mma_bf16(acc[ti][mi][nf], alf[mi], bhf[nf*2], bhf[nf*2+1]);
                    mma_bf16(acc[ti][mi][nf], ahf[mi], blf[nf*2], blf[nf*2+1]);
                }
        }
    }

    // ---- writeback ----
#pragma unroll
    for (int ti = 0; ti < 2; ti++) {
        int ct = t0 + ti;
#pragma unroll
        for (int mi = 0; mi < 2; mi++)
#pragma unroll
            for (int nf = 0; nf < 4; nf++) {
                int gr = m0 + wm * 32 + mi * 16 + (l >> 2);
                int co = ct * 64 + wn * 32 + nf * 8 + 2 * (l & 3);
                float2 v0 = make_float2(acc[ti][mi][nf][0], acc[ti][mi][nf][1]);
                float2 v1 = make_float2(acc[ti][mi][nf][2], acc[ti][mi][nf][3]);
                if (ct < 17) {
                    if (gr < NN)
                        *reinterpret_cast<float2*>(g_PQ + (size_t)gr * NCOL + co) = v0;
                    if (gr + 8 < NN)
                        *reinterpret_cast<float2*>(g_PQ + (size_t)(gr + 8) * NCOL + co) = v1;
                } else {
                    int cr = co - NCOL;
                    if (gr < NN)
                        *reinterpret_cast<float2*>(xrout + (size_t)gr * EMB + cr) = v0;
                    if (gr + 8 < NN)
                        *reinterpret_cast<float2*>(xrout + (size_t)(gr + 8) * EMB + cr) = v1;
                }
            }
    }
}

// ---------------- per-edge message + scatter (2 edges/warp, vec) ----------
__global__ __launch_bounds__(256) void edge_msg_kernel(const int* __restrict__ ei, int conv)
{
    int gw   = (blockIdx.x * 256 + threadIdx.x) >> 5;
    int lane = threadIdx.x & 31;
    int e    = gw * 2 + (lane >> 4);
    int sub  = lane & 15;
    if (e >= EE) return;

    const float* __restrict__ hsrc = conv ? g_h1 : g_h0;
    float* __restrict__ agg = (conv == 0) ? g_agg0 : (conv == 1 ? g_agg1 : g_agg2);

    int src = ei[e];
    int dst = ei[EE + e];
    float hv = hsrc[(size_t)e * HID + sub];

    const float* __restrict__ P = g_PQ + (size_t)src * NCOL;
    float4 acc = *reinterpret_cast<const float4*>(P + QOFF + sub * 4);
#pragma unroll
    for (int h = 0; h < HID; h++) {
        float w = __shfl_sync(0xffffffffu, hv, (lane & 16) | h);
        float4 f = *reinterpret_cast<const float4*>(P + h * EMB + sub * 4);
        acc.x += w * f.x; acc.y += w * f.y; acc.z += w * f.z; acc.w += w * f.w;
    }
    float* a = agg + (size_t)dst * EMB + sub * 4;
    asm volatile("red.global.add.v4.f32 [%0], {%1,%2,%3,%4};"
                 :: "l"(a), "f"(acc.x), "f"(acc.y), "f"(acc.z), "f"(acc.w)
                 : "memory");
}

// ---------------- pool + fused head (last-block pattern) -------------------
#define POOL_BLOCKS ((NN + 31) / 32)

__global__ __launch_bounds__(256) void pool_head_kernel(
    const int* __restrict__ batch, const float* __restrict__ bias2,
    const float* __restrict__ lin0w, const float* __restrict__ lin0b,
    const float* __restrict__ lin1w, const float* __restrict__ lin1b,
    float* __restrict__ out)
{
    int tid = threadIdx.x;
    int o = tid & 63, seg = tid >> 6;
    int n0 = blockIdx.x * 32 + seg * 8;
    float bz = __ldg(bias2 + o);
    int curb = -1;
    float m = 0.f;
    for (int k = 0; k < 8; k++) {
        int n = n0 + k;
        if (n >= NN) break;
        int b = batch[n];
        if (b != curb) {
            if (curb >= 0)
                atomicMax(reinterpret_cast<unsigned*>(g_pool + (size_t)curb * EMB + o),
                          __float_as_uint(m));
            curb = b;
            m = 0.f;
        }
        float x = fmaxf(g_agg2[(size_t)n * EMB + o] + g_xr2[(size_t)n * EMB + o] + bz, 0.f);
        m = fmaxf(m, x);
    }
    if (curb >= 0)
        atomicMax(reinterpret_cast<unsigned*>(g_pool + (size_t)curb * EMB + o),
                  __float_as_uint(m));

    // ---- last block performs the head ----
    __shared__ unsigned slast;
    __threadfence();
    __syncthreads();
    if (tid == 0) {
        unsigned t = atomicAdd(&g_cnt, 1u);
        slast = (t == POOL_BLOCKS - 1) ? 1u : 0u;
    }
    __syncthreads();
    if (!slast) return;
    __threadfence();

    __shared__ float pg[NG * EMB];
    for (int i = tid; i < NG * EMB; i += 256)
        pg[i] = __ldcg(g_pool + i);
    __syncthreads();

    // thread tid: graph g = tid>>2, o-range quarter q = tid&3
    int g = tid >> 2, q = tid & 3;
    float part = 0.f;
#pragma unroll
    for (int oo = 0; oo < 16; oo++) {
        int oc = q * 16 + oo;
        float h = lin0b[oc];
#pragma unroll
        for (int i = 0; i < EMB; i++) h += pg[g * EMB + i] * lin0w[i * EMB + oc];
        part += h * lin1w[oc];
    }
    part += __shfl_down_sync(0xffffffffu, part, 1);
    part += __shfl_down_sync(0xffffffffu, part, 2);
    if (q == 0) out[g] = part + lin1b[0];

    if (tid == 0) g_cnt = 0;   // reset for next replay (deterministic)
}

// ---------------- launch ----------------------------------------------------
extern "C" void kernel_launch(void* const* d_in, const int* in_sizes, int n_in,
                              void* d_out, int out_size)
{
    const float* x_p    = (const float*)d_in[0];
    const float* ea     = (const float*)d_in[2];
    const int*   ei     = (const int*)  d_in[4];
    const int*   batch  = (const int*)  d_in[5];
    const float* nn0_w1 = (const float*)d_in[6];
    const float* nn0_b1 = (const float*)d_in[7];
    const float* nn0_w2 = (const float*)d_in[8];
    const float* nn0_b2 = (const float*)d_in[9];
    const float* nn1_w1 = (const float*)d_in[10];
    const float* nn1_b1 = (const float*)d_in[11];
    const float* nn1_w2 = (const float*)d_in[12];
    const float* nn1_b2 = (const float*)d_in[13];
    const float* root0  = (const float*)d_in[14];
    const float* bias0  = (const float*)d_in[15];
    const float* root1  = (const float*)d_in[16];
    const float* bias1  = (const float*)d_in[17];
    const float* root2  = (const float*)d_in[18];
    const float* bias2  = (const float*)d_in[19];
    const float* lin0_w = (const float*)d_in[20];
    const float* lin0_b = (const float*)d_in[21];
    const float* lin1_w = (const float*)d_in[22];
    const float* lin1_b = (const float*)d_in[23];
    float* out = (float*)d_out;

    // smem: A 128*SD*2*2 + B 2*64*SD*2*2 bytes
    int smem32 = (128 * 40 * 4) + (2 * 64 * 40 * 4);   // 20480 + 20480 = 40960
    int smem64 = (128 * 72 * 4) + (2 * 64 * 72 * 4);   // 36864 + 36864 = 73728

    static bool attr_done = false;
    if (!attr_done) {
        cudaFuncSetAttribute(gemm_fused_kernel<64, 1>,
                             cudaFuncAttributeMaxDynamicSharedMemorySize, smem64);
        cudaFuncSetAttribute(gemm_fused_kernel<64, 2>,
                             cudaFuncAttributeMaxDynamicSharedMemorySize, smem64);
        attr_done = true;
    }

    dim3 gemm_grid(9, (NN + 127) / 128);
    int msg_blocks = EE / 16;

    prep_kernel<<<TR_BLOCKS + EH_BLOCKS, 256>>>(
        ea, nn0_w1, nn0_b1, nn0_w2, nn0_b2, nn1_w1, nn1_b1, nn1_w2, nn1_b2,
        root0, root1, root2);

    // ---- conv0 ----
    gemm_fused_kernel<32, 0><<<gemm_grid, 256, smem32>>>(x_p, bias0);
    edge_msg_kernel<<<msg_blocks, 256>>>(ei, 0);

    // ---- conv1 ----
    gemm_fused_kernel<64, 1><<<gemm_grid, 256, smem64>>>(nullptr, bias0);
    edge_msg_kernel<<<msg_blocks, 256>>>(ei, 1);

    // ---- conv2 ----
    gemm_fused_kernel<64, 2><<<gemm_grid, 256, smem64>>>(nullptr, bias1);
    edge_msg_kernel<<<msg_blocks, 256>>>(ei, 2);

    // ---- pool + head (fused) ----
    pool_head_kernel<<<POOL_BLOCKS, 256>>>(batch, bias2,
                                           lin0_w, lin0_b, lin1_w, lin1_b, out);
}

// round 7
// speedup vs baseline: 1.1541x; 1.1541x over previous
#include <cuda_runtime.h>
#include <cuda_bf16.h>
#include <cstdint>

#define NN      10000
#define EE      30000
#define FEDGE   8
#define EMB     64
#define HID     16
#define NG      64
#define NCOL    1088   // 1024 P | 64 Q
#define QOFF    1024

// ---------------- scratch (device globals) --------------------------------
__device__ __align__(128) float g_h0[EE * HID];
__device__ __align__(128) float g_h1[EE * HID];
__device__ __align__(128) float g_PQ[(size_t)NN * NCOL];
__device__ __align__(128) float g_agg0[NN * EMB];
__device__ __align__(128) float g_agg1[NN * EMB];
__device__ __align__(128) float g_agg2[NN * EMB];
__device__ __align__(128) float g_xr0[NN * EMB];
__device__ __align__(128) float g_xr1[NN * EMB];
__device__ __align__(128) float g_xr2[NN * EMB];
// pre-converted bf16 hi/lo B matrices, [tile][o][i]
__device__ __align__(128) ushort g_W0h[18 * 64 * 32], g_W0l[18 * 64 * 32]; // conv0 P,Q + root0(t17)
__device__ __align__(128) ushort g_W1h[17 * 64 * 64], g_W1l[17 * 64 * 64]; // convs 1&2 P,Q
__device__ __align__(128) ushort g_R1h[64 * 64], g_R1l[64 * 64];
__device__ __align__(128) ushort g_R2h[64 * 64], g_R2l[64 * 64];
__device__ __align__(128) float g_pool[NG * EMB];
__device__ unsigned g_cnt = 0;

// ---------------- helpers --------------------------------------------------
__device__ __forceinline__ uint32_t smem_u32(const void* p) {
    uint32_t a;
    asm("{ .reg .u64 t; cvta.to.shared.u64 t, %1; cvt.u32.u64 %0, t; }" : "=r"(a) : "l"(p));
    return a;
}
__device__ __forceinline__ void ldmx4(uint32_t* r, uint32_t addr) {
    asm volatile("ldmatrix.sync.aligned.m8n8.x4.shared.b16 {%0,%1,%2,%3}, [%4];"
        : "=r"(r[0]), "=r"(r[1]), "=r"(r[2]), "=r"(r[3]) : "r"(addr));
}
__device__ __forceinline__ void mma_bf16(float* d, const uint32_t* a,
                                         uint32_t b0, uint32_t b1) {
    asm volatile("mma.sync.aligned.m16n8k16.row.col.f32.bf16.bf16.f32 "
        "{%0,%1,%2,%3}, {%4,%5,%6,%7}, {%8,%9}, {%0,%1,%2,%3};"
        : "+f"(d[0]), "+f"(d[1]), "+f"(d[2]), "+f"(d[3])
        : "r"(a[0]), "r"(a[1]), "r"(a[2]), "r"(a[3]), "r"(b0), "r"(b1));
}
__device__ __forceinline__ void split_pack(float fx, float fy,
                                           uint32_t& hi, uint32_t& lo) {
    __nv_bfloat16 hx = __float2bfloat16(fx), hy = __float2bfloat16(fy);
    hi = ((uint32_t)__bfloat16_as_ushort(hy) << 16) | __bfloat16_as_ushort(hx);
    __nv_bfloat16 lx = __float2bfloat16(fx - __bfloat162float(hx));
    __nv_bfloat16 ly = __float2bfloat16(fy - __bfloat162float(hy));
    lo = ((uint32_t)__bfloat16_as_ushort(ly) << 16) | __bfloat16_as_ushort(lx);
}
__device__ __forceinline__ void split_us(float v, ushort& hi, ushort& lo) {
    __nv_bfloat16 h = __float2bfloat16(v);
    hi = __bfloat16_as_ushort(h);
    lo = __bfloat16_as_ushort(__float2bfloat16(v - __bfloat162float(h)));
}

// ---------------- prep: transpose + bf16-split B, edge MLP hiddens ---------
#define TR_BLOCKS 37
#define EH_BLOCKS ((EE + 255) / 256)

__global__ __launch_bounds__(256) void prep_kernel(
    const float* __restrict__ ea,
    const float* __restrict__ nn0_w1, const float* __restrict__ nn0_b1,
    const float* __restrict__ nn0_w2, const float* __restrict__ nn0_b2,
    const float* __restrict__ nn1_w1, const float* __restrict__ nn1_b1,
    const float* __restrict__ nn1_w2, const float* __restrict__ nn1_b2,
    const float* __restrict__ root0, const float* __restrict__ root1,
    const float* __restrict__ root2)
{
    int tid = threadIdx.x;
    int b = blockIdx.x;

    if (b < TR_BLOCKS) {
        __shared__ float ts[64 * 65];
        const float* src;
        ushort *dsth, *dstl;
        int D;
        if (b < 17) {
            D = 32; src = (b < 16) ? nn0_w2 + b * 2048 : nn0_b2;
            dsth = g_W0h + b * 2048; dstl = g_W0l + b * 2048;
        } else if (b == 17) {
            D = 32; src = root0;
            dsth = g_W0h + 17 * 2048; dstl = g_W0l + 17 * 2048;
        } else if (b < 35) {
            int bb = b - 18; D = 64;
            src = (bb < 16) ? nn1_w2 + bb * 4096 : nn1_b2;
            dsth = g_W1h + bb * 4096; dstl = g_W1l + bb * 4096;
        } else if (b == 35) { D = 64; src = root1; dsth = g_R1h; dstl = g_R1l; }
        else               { D = 64; src = root2; dsth = g_R2h; dstl = g_R2l; }

        for (int idx = tid; idx < 64 * D; idx += 256) {
            int o = idx & 63, i = idx >> 6;
            ts[o * 65 + i] = src[i * 64 + o];
        }
        __syncthreads();
        for (int idx = tid; idx < 64 * D; idx += 256) {
            int i = idx & (D - 1), o = idx / D;
            ushort hi, lo;
            split_us(ts[o * 65 + i], hi, lo);
            dsth[idx] = hi;
            dstl[idx] = lo;
        }
        return;
    }

    __shared__ float sw0[FEDGE * HID], sw1[FEDGE * HID];
    __shared__ float sb0[HID], sb1[HID];
    if (tid < FEDGE * HID) { sw0[tid] = nn0_w1[tid]; sw1[tid] = nn1_w1[tid]; }
    if (tid < HID)         { sb0[tid] = nn0_b1[tid]; sb1[tid] = nn1_b1[tid]; }
    __syncthreads();

    int e = (b - TR_BLOCKS) * 256 + tid;
    if (e >= EE) return;
    const float4* p = reinterpret_cast<const float4*>(ea + (size_t)e * FEDGE);
    float4 v0 = p[0], v1 = p[1];
    float a[8] = {v0.x, v0.y, v0.z, v0.w, v1.x, v1.y, v1.z, v1.w};
#pragma unroll
    for (int h = 0; h < HID; h++) {
        float s0 = sb0[h], s1 = sb1[h];
#pragma unroll
        for (int j = 0; j < FEDGE; j++) {
            s0 += a[j] * sw0[j * HID + h];
            s1 += a[j] * sw1[j * HID + h];
        }
        g_h0[e * HID + h] = fmaxf(s0, 0.f);
        g_h1[e * HID + h] = fmaxf(s1, 0.f);
    }
}

// ---------------- fused HMMA GEMM (R5 structure: tile-inner loop) ---------
// [x | relu(agg+xr+bias)] (128 rows) @ WT^T, 2 column tiles per block.
// Tiles 0..16 -> g_PQ, tile 17 -> g_xr. Zeroes next agg. A staged once.
template <int D, int MODE>
__global__ __launch_bounds__(256, 3) void gemm_fused_kernel(
    const float* __restrict__ xin, const float* __restrict__ biasin)
{
    const int SD = D + 8;
    const int CPT = D / 8;
    extern __shared__ ushort smu[];
    ushort* Ah = smu;                   // 128*SD
    ushort* Al = Ah + 128 * SD;
    ushort* Bh = Al + 128 * SD;         // 64*SD (single tile)
    ushort* Bl = Bh + 64 * SD;
    __shared__ float sbias[64];

    const float* __restrict__ aggin = (MODE == 1) ? g_agg0 : g_agg1;
    const float* __restrict__ xrin  = (MODE == 1) ? g_xr0  : g_xr1;
    float* __restrict__ aggz  = (MODE == 0) ? g_agg0 : (MODE == 1 ? g_agg1 : g_agg2);
    float* __restrict__ xrout = (MODE == 0) ? g_xr0  : (MODE == 1 ? g_xr1  : g_xr2);
    const ushort* __restrict__ WTh = (MODE == 0) ? g_W0h : g_W1h;
    const ushort* __restrict__ WTl = (MODE == 0) ? g_W0l : g_W1l;
    const ushort* __restrict__ RTh = (MODE == 0) ? (g_W0h + 17 * 2048)
                                                 : (MODE == 1 ? g_R1h : g_R2h);
    const ushort* __restrict__ RTl = (MODE == 0) ? (g_W0l + 17 * 2048)
                                                 : (MODE == 1 ? g_R1l : g_R2l);

    int tid = threadIdx.x, wid = tid >> 5, l = tid & 31;
    int wm = wid & 3, wn = wid >> 2;
    int m0 = blockIdx.y * 128;
    int t0 = blockIdx.x * 2;

    // zero next agg buffer
    {
        int nthr = gridDim.x * gridDim.y * 256;
        for (int i = (blockIdx.y * gridDim.x + blockIdx.x) * 256 + tid;
             i < NN * EMB; i += nthr)
            aggz[i] = 0.f;
    }
    if (MODE && tid < 64) sbias[tid] = biasin[tid];
    if (MODE) __syncthreads();

    // ---- stage A once (full D), fp32 -> bf16 hi/lo ----
    for (int idx = tid; idx < 128 * CPT; idx += 256) {
        int r = idx / CPT, cb = (idx % CPT) * 8;
        int n = m0 + r;
        bool v = (n < NN);
        float vals[8];
        if (MODE == 0) {
            float4 a0 = make_float4(0.f, 0.f, 0.f, 0.f), a1 = a0;
            if (v) {
                a0 = *reinterpret_cast<const float4*>(xin + (size_t)n * D + cb);
                a1 = *reinterpret_cast<const float4*>(xin + (size_t)n * D + cb + 4);
            }
            vals[0]=a0.x; vals[1]=a0.y; vals[2]=a0.z; vals[3]=a0.w;
            vals[4]=a1.x; vals[5]=a1.y; vals[6]=a1.z; vals[7]=a1.w;
        } else {
            float4 g0 = make_float4(0.f,0.f,0.f,0.f), g1 = g0, r0 = g0, r1 = g0;
            if (v) {
                g0 = *reinterpret_cast<const float4*>(aggin + (size_t)n * EMB + cb);
                g1 = *reinterpret_cast<const float4*>(aggin + (size_t)n * EMB + cb + 4);
                r0 = *reinterpret_cast<const float4*>(xrin + (size_t)n * EMB + cb);
                r1 = *reinterpret_cast<const float4*>(xrin + (size_t)n * EMB + cb + 4);
            }
            vals[0] = fmaxf(g0.x + r0.x + sbias[cb+0], 0.f);
            vals[1] = fmaxf(g0.y + r0.y + sbias[cb+1], 0.f);
            vals[2] = fmaxf(g0.z + r0.z + sbias[cb+2], 0.f);
            vals[3] = fmaxf(g0.w + r0.w + sbias[cb+3], 0.f);
            vals[4] = fmaxf(g1.x + r1.x + sbias[cb+4], 0.f);
            vals[5] = fmaxf(g1.y + r1.y + sbias[cb+5], 0.f);
            vals[6] = fmaxf(g1.z + r1.z + sbias[cb+6], 0.f);
            vals[7] = fmaxf(g1.w + r1.w + sbias[cb+7], 0.f);
        }
        uint32_t* ah32 = reinterpret_cast<uint32_t*>(Ah);
        uint32_t* al32 = reinterpret_cast<uint32_t*>(Al);
        int base = (r * SD + cb) >> 1;
#pragma unroll
        for (int j = 0; j < 4; j++) {
            uint32_t hi, lo;
            split_pack(vals[2*j], vals[2*j+1], hi, lo);
            ah32[base + j] = hi;
            al32[base + j] = lo;
        }
    }

    uint32_t aAh = smem_u32(Ah), aAl = smem_u32(Al);
    uint32_t aBh = smem_u32(Bh), aBl = smem_u32(Bl);

#pragma unroll
    for (int ti = 0; ti < 2; ti++) {
        int ct = t0 + ti;
        const ushort* bh = (ct == 17) ? RTh : WTh + (size_t)ct * 64 * D;
        const ushort* bl = (ct == 17) ? RTl : WTl + (size_t)ct * 64 * D;

        // ---- stage B tile: pure uint4 copies of pre-split bf16 ----
        for (int idx = tid; idx < 64 * CPT; idx += 256) {
            int r = idx / CPT, cb8 = idx % CPT;
            uint4 vh = *reinterpret_cast<const uint4*>(bh + r * D + cb8 * 8);
            uint4 vl = *reinterpret_cast<const uint4*>(bl + r * D + cb8 * 8);
            *reinterpret_cast<uint4*>(Bh + r * SD + cb8 * 8) = vh;
            *reinterpret_cast<uint4*>(Bl + r * SD + cb8 * 8) = vl;
        }
        __syncthreads();   // covers A-stage (iter 0) + B-stage

        float acc[2][4][4];
#pragma unroll
        for (int mi = 0; mi < 2; mi++)
#pragma unroll
            for (int nf = 0; nf < 4; nf++)
#pragma unroll
                for (int q = 0; q < 4; q++) acc[mi][nf][q] = 0.f;

#pragma unroll
        for (int ks = 0; ks < D; ks += 16) {
            uint32_t ahf[2][4], alf[2][4];
#pragma unroll
            for (int mi = 0; mi < 2; mi++) {
                uint32_t off = ((uint32_t)(wm * 32 + mi * 16 + (l & 15)) * SD
                                + ks + (l >> 4) * 8) * 2;
                ldmx4(ahf[mi], aAh + off);
                ldmx4(alf[mi], aAl + off);
            }
            uint32_t bhf[8], blf[8];
#pragma unroll
            for (int g = 0; g < 2; g++) {
                uint32_t off = ((uint32_t)(wn * 32 + g * 16 + (l & 7) + ((l >> 4) & 1) * 8) * SD
                                + ks + ((l >> 3) & 1) * 8) * 2;
                ldmx4(bhf + g * 4, aBh + off);
                ldmx4(blf + g * 4, aBl + off);
            }
#pragma unroll
            for (int mi = 0; mi < 2; mi++)
#pragma unroll
                for (int nf = 0; nf < 4; nf++) {
                    mma_bf16(acc[mi][nf], ahf[mi], bhf[nf*2], bhf[nf*2+1]);
                    mma_bf16(acc[mi][nf], alf[mi], bhf[nf*2], bhf[nf*2+1]);
                    mma_bf16(acc[mi][nf], ahf[mi], blf[nf*2], blf[nf*2+1]);
                }
        }

        // ---- writeback ----
#pragma unroll
        for (int mi = 0; mi < 2; mi++)
#pragma unroll
            for (int nf = 0; nf < 4; nf++) {
                int gr = m0 + wm * 32 + mi * 16 + (l >> 2);
                int co = ct * 64 + wn * 32 + nf * 8 + 2 * (l & 3);
                float2 v0 = make_float2(acc[mi][nf][0], acc[mi][nf][1]);
                float2 v1 = make_float2(acc[mi][nf][2], acc[mi][nf][3]);
                if (ct < 17) {
                    if (gr < NN)
                        *reinterpret_cast<float2*>(g_PQ + (size_t)gr * NCOL + co) = v0;
                    if (gr + 8 < NN)
                        *reinterpret_cast<float2*>(g_PQ + (size_t)(gr + 8) * NCOL + co) = v1;
                } else {
                    int cr = co - NCOL;
                    if (gr < NN)
                        *reinterpret_cast<float2*>(xrout + (size_t)gr * EMB + cr) = v0;
                    if (gr + 8 < NN)
                        *reinterpret_cast<float2*>(xrout + (size_t)(gr + 8) * EMB + cr) = v1;
                }
            }
        __syncthreads();
    }
}

// ---------------- per-edge message + scatter (2 edges/warp, vec) ----------
__global__ __launch_bounds__(256) void edge_msg_kernel(const int* __restrict__ ei, int conv)
{
    int gw   = (blockIdx.x * 256 + threadIdx.x) >> 5;
    int lane = threadIdx.x & 31;
    int e    = gw * 2 + (lane >> 4);
    int sub  = lane & 15;
    if (e >= EE) return;

    const float* __restrict__ hsrc = conv ? g_h1 : g_h0;
    float* __restrict__ agg = (conv == 0) ? g_agg0 : (conv == 1 ? g_agg1 : g_agg2);

    int src = ei[e];
    int dst = ei[EE + e];
    float hv = hsrc[(size_t)e * HID + sub];

    const float* __restrict__ P = g_PQ + (size_t)src * NCOL;
    float4 acc = *reinterpret_cast<const float4*>(P + QOFF + sub * 4);
#pragma unroll
    for (int h = 0; h < HID; h++) {
        float w = __shfl_sync(0xffffffffu, hv, (lane & 16) | h);
        float4 f = *reinterpret_cast<const float4*>(P + h * EMB + sub * 4);
        acc.x += w * f.x; acc.y += w * f.y; acc.z += w * f.z; acc.w += w * f.w;
    }
    float* a = agg + (size_t)dst * EMB + sub * 4;
    asm volatile("red.global.add.v4.f32 [%0], {%1,%2,%3,%4};"
                 :: "l"(a), "f"(acc.x), "f"(acc.y), "f"(acc.z), "f"(acc.w)
                 : "memory");
}

// ---------------- pool + fused head (last-block pattern) -------------------
#define POOL_BLOCKS ((NN + 31) / 32)

__global__ __launch_bounds__(256) void pool_head_kernel(
    const int* __restrict__ batch, const float* __restrict__ bias2,
    const float* __restrict__ lin0w, const float* __restrict__ lin0b,
    const float* __restrict__ lin1w, const float* __restrict__ lin1b,
    float* __restrict__ out)
{
    int tid = threadIdx.x;
    int o = tid & 63, seg = tid >> 6;
    int n0 = blockIdx.x * 32 + seg * 8;
    float bz = __ldg(bias2 + o);
    int curb = -1;
    float m = 0.f;
    for (int k = 0; k < 8; k++) {
        int n = n0 + k;
        if (n >= NN) break;
        int b = batch[n];
        if (b != curb) {
            if (curb >= 0)
                atomicMax(reinterpret_cast<unsigned*>(g_pool + (size_t)curb * EMB + o),
                          __float_as_uint(m));
            curb = b;
            m = 0.f;
        }
        float x = fmaxf(g_agg2[(size_t)n * EMB + o] + g_xr2[(size_t)n * EMB + o] + bz, 0.f);
        m = fmaxf(m, x);
    }
    if (curb >= 0)
        atomicMax(reinterpret_cast<unsigned*>(g_pool + (size_t)curb * EMB + o),
                  __float_as_uint(m));

    // ---- last block performs the head ----
    __shared__ unsigned slast;
    __threadfence();
    __syncthreads();
    if (tid == 0) {
        unsigned t = atomicAdd(&g_cnt, 1u);
        slast = (t == POOL_BLOCKS - 1) ? 1u : 0u;
    }
    __syncthreads();
    if (!slast) return;
    __threadfence();

    __shared__ float pg[NG * EMB];
    for (int i = tid; i < NG * EMB; i += 256)
        pg[i] = __ldcg(g_pool + i);
    __syncthreads();

    int g = tid >> 2, q = tid & 3;
    float part = 0.f;
#pragma unroll
    for (int oo = 0; oo < 16; oo++) {
        int oc = q * 16 + oo;
        float h = lin0b[oc];
#pragma unroll
        for (int i = 0; i < EMB; i++) h += pg[g * EMB + i] * lin0w[i * EMB + oc];
        part += h * lin1w[oc];
    }
    part += __shfl_down_sync(0xffffffffu, part, 1);
    part += __shfl_down_sync(0xffffffffu, part, 2);
    if (q == 0) out[g] = part + lin1b[0];

    if (tid == 0) g_cnt = 0;   // reset for next replay
}

// ---------------- launch ----------------------------------------------------
extern "C" void kernel_launch(void* const* d_in, const int* in_sizes, int n_in,
                              void* d_out, int out_size)
{
    const float* x_p    = (const float*)d_in[0];
    const float* ea     = (const float*)d_in[2];
    const int*   ei     = (const int*)  d_in[4];
    const int*   batch  = (const int*)  d_in[5];
    const float* nn0_w1 = (const float*)d_in[6];
    const float* nn0_b1 = (const float*)d_in[7];
    const float* nn0_w2 = (const float*)d_in[8];
    const float* nn0_b2 = (const float*)d_in[9];
    const float* nn1_w1 = (const float*)d_in[10];
    const float* nn1_b1 = (const float*)d_in[11];
    const float* nn1_w2 = (const float*)d_in[12];
    const float* nn1_b2 = (const float*)d_in[13];
    const float* root0  = (const float*)d_in[14];
    const float* bias0  = (const float*)d_in[15];
    const float* root1  = (const float*)d_in[16];
    const float* bias1  = (const float*)d_in[17];
    const float* root2  = (const float*)d_in[18];
    const float* bias2  = (const float*)d_in[19];
    const float* lin0_w = (const float*)d_in[20];
    const float* lin0_b = (const float*)d_in[21];
    const float* lin1_w = (const float*)d_in[22];
    const float* lin1_b = (const float*)d_in[23];
    float* out = (float*)d_out;

    // smem: A 128*SD*4 + B 64*SD*4 bytes
    int smem32 = 128 * 40 * 4 + 64 * 40 * 4;   // 30720
    int smem64 = 128 * 72 * 4 + 64 * 72 * 4;   // 55296

    static bool attr_done = false;
    if (!attr_done) {
        cudaFuncSetAttribute(gemm_fused_kernel<64, 1>,
                             cudaFuncAttributeMaxDynamicSharedMemorySize, smem64);
        cudaFuncSetAttribute(gemm_fused_kernel<64, 2>,
                             cudaFuncAttributeMaxDynamicSharedMemorySize, smem64);
        attr_done = true;
    }

    dim3 gemm_grid(9, (NN + 127) / 128);
    int msg_blocks = EE / 16;

    prep_kernel<<<TR_BLOCKS + EH_BLOCKS, 256>>>(
        ea, nn0_w1, nn0_b1, nn0_w2, nn0_b2, nn1_w1, nn1_b1, nn1_w2, nn1_b2,
        root0, root1, root2);

    // ---- conv0 ----
    gemm_fused_kernel<32, 0><<<gemm_grid, 256, smem32>>>(x_p, bias0);
    edge_msg_kernel<<<msg_blocks, 256>>>(ei, 0);

    // ---- conv1 ----
    gemm_fused_kernel<64, 1><<<gemm_grid, 256, smem64>>>(nullptr, bias0);
    edge_msg_kernel<<<msg_blocks, 256>>>(ei, 1);

    // ---- conv2 ----
    gemm_fused_kernel<64, 2><<<gemm_grid, 256, smem64>>>(nullptr, bias1);
    edge_msg_kernel<<<msg_blocks, 256>>>(ei, 2);

    // ---- pool + head (fused) ----
    pool_head_kernel<<<POOL_BLOCKS, 256>>>(batch, bias2,
                                           lin0_w, lin0_b, lin1_w, lin1_b, out);
}